// round 1
// baseline (speedup 1.0000x reference)
#include <cuda_runtime.h>
#include <math.h>

#define BATCH 1024
#define OBS_DIM 256
#define HIDDEN_DIM 512
#define ACTION_DIM 18
#define ETA 0.01f
#define LAMBDA 0.95f

// scratch for hidden activations (allocation-free rule: static __device__ array)
__device__ float g_hidden[BATCH * HIDDEN_DIM];

// One warp per (b, h) row. 8 warps / block share one batch's obs vector in smem.
// M row (256 f32) lives entirely in registers: single pass read + single pass write.
__global__ __launch_bounds__(256, 8) void mpn_main_kernel(
    const float* __restrict__ obs,
    const float* __restrict__ M,
    const float* __restrict__ W,
    const float* __restrict__ b_h,
    float* __restrict__ newM)
{
    const int b    = blockIdx.x >> 6;        // 64 h-groups per batch (512/8)
    const int hg   = blockIdx.x & 63;
    const int warp = threadIdx.x >> 5;
    const int lane = threadIdx.x & 31;
    const int h    = hg * 8 + warp;

    __shared__ float4 s_obs[64];             // 256 floats = 1KB
    if (threadIdx.x < 64)
        s_obs[threadIdx.x] = reinterpret_cast<const float4*>(obs + b * OBS_DIM)[threadIdx.x];
    __syncthreads();

    const size_t row = ((size_t)b * HIDDEN_DIM + h) * OBS_DIM;
    const float4* Mrow = reinterpret_cast<const float4*>(M + row);
    const float4* Wrow = reinterpret_cast<const float4*>(W + (size_t)h * OBS_DIM);
    float4* Nrow = reinterpret_cast<float4*>(newM + row);

    // coalesced: lanes cover float4[0..31] and float4[32..63] of the row
    float4 m0 = Mrow[lane];
    float4 m1 = Mrow[lane + 32];
    float4 w0 = Wrow[lane];
    float4 w1 = Wrow[lane + 32];
    float4 o0 = s_obs[lane];
    float4 o1 = s_obs[lane + 32];

    // acc = sum_o W*(1+M)*obs   (== base + plastic)
    float acc;
    acc  = w0.x * (1.0f + m0.x) * o0.x;
    acc += w0.y * (1.0f + m0.y) * o0.y;
    acc += w0.z * (1.0f + m0.z) * o0.z;
    acc += w0.w * (1.0f + m0.w) * o0.w;
    acc += w1.x * (1.0f + m1.x) * o1.x;
    acc += w1.y * (1.0f + m1.y) * o1.y;
    acc += w1.z * (1.0f + m1.z) * o1.z;
    acc += w1.w * (1.0f + m1.w) * o1.w;

    #pragma unroll
    for (int off = 16; off > 0; off >>= 1)
        acc += __shfl_xor_sync(0xffffffffu, acc, off);

    const float hval = tanhf(acc + __ldg(&b_h[h]));   // same value in all lanes

    // Hebbian update written from registers already in hand
    float4 n0, n1;
    const float eh = ETA * hval;
    n0.x = LAMBDA * m0.x + eh * o0.x;
    n0.y = LAMBDA * m0.y + eh * o0.y;
    n0.z = LAMBDA * m0.z + eh * o0.z;
    n0.w = LAMBDA * m0.w + eh * o0.w;
    n1.x = LAMBDA * m1.x + eh * o1.x;
    n1.y = LAMBDA * m1.y + eh * o1.y;
    n1.z = LAMBDA * m1.z + eh * o1.z;
    n1.w = LAMBDA * m1.w + eh * o1.w;
    Nrow[lane]      = n0;
    Nrow[lane + 32] = n1;

    if (lane == 0)
        g_hidden[b * HIDDEN_DIM + h] = hval;
}

// q[b,a] = sum_h hidden[b,h] * Wq[a,h] + bq[a]
// one block per batch element, one warp per action (18 warps = 576 threads)
__global__ __launch_bounds__(576) void q_head_kernel(
    const float* __restrict__ Wq,
    const float* __restrict__ bq,
    float* __restrict__ q)
{
    const int b    = blockIdx.x;
    const int a    = threadIdx.x >> 5;   // 0..17
    const int lane = threadIdx.x & 31;

    const float* hrow  = g_hidden + (size_t)b * HIDDEN_DIM;
    const float* wqrow = Wq + (size_t)a * HIDDEN_DIM;

    float acc = 0.0f;
    #pragma unroll
    for (int hh = lane; hh < HIDDEN_DIM; hh += 32)
        acc += hrow[hh] * wqrow[hh];

    #pragma unroll
    for (int off = 16; off > 0; off >>= 1)
        acc += __shfl_xor_sync(0xffffffffu, acc, off);

    if (lane == 0)
        q[(size_t)b * ACTION_DIM + a] = acc + bq[a];
}

extern "C" void kernel_launch(void* const* d_in, const int* in_sizes, int n_in,
                              void* d_out, int out_size)
{
    const float* obs = (const float*)d_in[0];   // [B, O]
    const float* M   = (const float*)d_in[1];   // [B, H, O]
    const float* W   = (const float*)d_in[2];   // [H, O]
    const float* b_h = (const float*)d_in[3];   // [H]
    const float* Wq  = (const float*)d_in[4];   // [A, H]
    const float* bq  = (const float*)d_in[5];   // [A]

    float* out  = (float*)d_out;
    float* q    = out;                              // [B, A]
    float* newM = out + (size_t)BATCH * ACTION_DIM; // [B, H, O]

    mpn_main_kernel<<<BATCH * (HIDDEN_DIM / 8), 256>>>(obs, M, W, b_h, newM);
    q_head_kernel<<<BATCH, ACTION_DIM * 32>>>(Wq, bq, q);
}